// round 10
// baseline (speedup 1.0000x reference)
#include <cuda_runtime.h>

#define CH 32
#define SEGS 33
#define NMAX 50000
#define EMAX 200000
#define FULL 0xffffffffu
#define NBLK 592
#define NWARP (NBLK * 4)
#define ACH 8

typedef unsigned long long ull;

// ---- device-global scratch ----
__device__ float g_bp_e[32], g_bp_a[32];          // compacted breakpoints
__device__ int   g_nseg_e, g_nseg_a;              // effective segment counts
// per segment: [0,512) = PA pairs {A[2k][o],A[2k+1][o]}, [512,1024) = PB pairs
__device__ ull   g_AB[SEGS * 1024];
__device__ float g_aA[SEGS * 32], g_aB[SEGS * 32];
__device__ int   g_ecnt[SEGS];                    // per-segment edge count / cursor
__device__ __align__(16) int4 g_ebuckp[SEGS * EMAX]; // packed {row, col, t_bits, 0}
__device__ __align__(16) float2 g_cts[SEGS * NMAX];  // (count, sum_t) per (seg, node)

// ---------------------------------------------------------------------------
// warp-level breakpoint extraction + rank sort into `sorted`; returns count.
// ---------------------------------------------------------------------------
__device__ __forceinline__ int bp_sort(const float* __restrict__ W,
                                       const float* __restrict__ Bv,
                                       int lane, float* sorted) {
    float w = W[lane], b = Bv[lane];
    float p = (w != 0.0f) ? (-b / w) : -1.0f;
    bool valid = (p > 0.0f && p < 1.0f);
    unsigned vm = __ballot_sync(FULL, valid);
    int c = __popc(vm);
    int rank = 0;
    #pragma unroll
    for (int i = 0; i < 32; i++) {
        float pi = __shfl_sync(FULL, p, i);
        bool vi = (vm >> i) & 1u;
        if (vi && (pi < p || (pi == p && i < lane))) rank++;
    }
    if (valid) sorted[rank] = p;
    __syncwarp();
    return c;
}

// ---------------------------------------------------------------------------
// K1: blocks 0..131: edge table, (segment = blk>>2, io-chunk = blk&3), 1 pass.
//     block 132: publish breakpoints + angle table + zero cursors.
//     blocks 133+: zero g_cts.
// ---------------------------------------------------------------------------
__global__ void k_setup(const float* __restrict__ eW1, const float* __restrict__ eb1,
                        const float* __restrict__ eW2, const float* __restrict__ eb2,
                        const float* __restrict__ aW1, const float* __restrict__ ab1,
                        const float* __restrict__ aW2, const float* __restrict__ ab2) {
    int blk = blockIdx.x;
    if (blk < 4 * SEGS) {
        int s = blk >> 2, chunk = blk & 3;
        __shared__ float sbp[33];
        __shared__ int scnt;
        __shared__ float w1[32], b1[32];
        if (threadIdx.x < 32) {
            int c = bp_sort(eW1, eb1, threadIdx.x, sbp);
            if (threadIdx.x == 0) scnt = c;
        }
        if (threadIdx.x >= 32 && threadIdx.x < 64) {
            int l = threadIdx.x - 32;
            w1[l] = eW1[l]; b1[l] = eb1[l];
        }
        __syncthreads();
        int c = scnt;
        if (s > c) return;                 // segment doesn't exist
        float lo = (s == 0) ? 0.0f : sbp[s - 1];
        float hi = (s == c) ? 1.0f : sbp[s];
        float trep = 0.5f * (lo + hi);
        int io = chunk * 256 + threadIdx.x;   // one io value per thread
        float a = eb2[io], b = 0.0f;
        #pragma unroll
        for (int k = 0; k < 32; k++) {
            if (w1[k] * trep + b1[k] > 0.0f) {
                float w2 = __ldg(eW2 + k * 1024 + io);
                a = fmaf(b1[k], w2, a);
                b = fmaf(w1[k], w2, b);
            }
        }
        int i = io >> 5, o = io & 31;
        int pa = s * 2048 + (i >> 1) * 64 + o * 2 + (i & 1);
        float* ABf = (float*)g_AB;
        ABf[pa] = a;
        ABf[pa + 1024] = b;
    } else if (blk == 4 * SEGS) {
        // ---- publish breakpoints + angle table + zero cursors ----
        __shared__ float se[33], sa[33];
        __shared__ int sca;
        int warp = threadIdx.x >> 5, lane = threadIdx.x & 31;
        if (threadIdx.x < SEGS) g_ecnt[threadIdx.x] = 0;
        if (warp == 0) {
            int c = bp_sort(eW1, eb1, lane, se);
            g_bp_e[lane] = (lane < c) ? se[lane] : 2.0f;
            if (lane == 0) g_nseg_e = c + 1;
        } else if (warp == 1) {
            int c = bp_sort(aW1, ab1, lane, sa);
            g_bp_a[lane] = (lane < c) ? sa[lane] : 2.0f;
            if (lane == 0) { g_nseg_a = c + 1; sca = c; }
        }
        __syncthreads();
        int ca = sca;
        int ns = ca + 1;
        for (int idx = threadIdx.x; idx < ns * 32; idx += blockDim.x) {
            int s2 = idx >> 5, o = idx & 31;
            float lo = (s2 == 0) ? 0.0f : sa[s2 - 1];
            float hi = (s2 == ca) ? 1.0f : sa[s2];
            float trep = 0.5f * (lo + hi);
            float a = ab2[o], b = 0.0f;
            #pragma unroll
            for (int k = 0; k < 32; k++) {
                float w = aW1[k], bb = ab1[k];
                if (w * trep + bb > 0.0f) {
                    float w2 = aW2[k * 32 + o];
                    a = fmaf(bb, w2, a);
                    b = fmaf(w, w2, b);
                }
            }
            g_aA[idx] = a;
            g_aB[idx] = b;
        }
    } else {
        // ---- zero g_cts (only the live segments) ----
        __shared__ int sna;
        if (threadIdx.x < 32) {
            float w = aW1[threadIdx.x], b = ab1[threadIdx.x];
            float p = (w != 0.0f) ? (-b / w) : -1.0f;
            unsigned vm = __ballot_sync(FULL, p > 0.0f && p < 1.0f);
            if (threadIdx.x == 0) sna = __popc(vm) + 1;
        }
        __syncthreads();
        float4 z = make_float4(0.f, 0.f, 0.f, 0.f);
        int nc = sna * (NMAX / 2);             // float4 count over g_cts
        int nb = gridDim.x - 4 * SEGS - 1;
        int gid = (blk - 4 * SEGS - 1) * blockDim.x + threadIdx.x;
        int stride = nb * blockDim.x;
        float4* c4 = (float4*)g_cts;
        for (int i = gid; i < nc; i += stride) c4[i] = z;
    }
}

// ---------------------------------------------------------------------------
// K2: front pass — packed edge bucketing (warp-aggregated) + angle scatter +
//     grid-stride zeroing of `out` (must precede k_edge's reds; stream order).
// ---------------------------------------------------------------------------
__global__ void k_front(const int* __restrict__ ei, const float* __restrict__ ea,
                        const int* __restrict__ ai, const float* __restrict__ ang,
                        float* __restrict__ out,
                        int E, int A, int N) {
    __shared__ float sbe[32], sba[32];
    if (threadIdx.x < 32) { sbe[threadIdx.x] = g_bp_e[threadIdx.x]; sba[threadIdx.x] = g_bp_a[threadIdx.x]; }
    __syncthreads();
    int i = blockIdx.x * blockDim.x + threadIdx.x;
    int lane = threadIdx.x & 31;
    int nbe = g_nseg_e - 1;
    int nba = g_nseg_a - 1;

    // ---- zero out (grid-stride, ~1 float4 per thread) ----
    {
        float4 z = make_float4(0.f, 0.f, 0.f, 0.f);
        int no = N * 8;
        int stride = gridDim.x * blockDim.x;
        float4* o4 = (float4*)out;
        for (int k = i; k < no; k += stride) o4[k] = z;
    }

    bool valid = (i < E);
    float t = valid ? __ldg(ea + i) : 0.0f;
    int r = valid ? __ldg(ei + i) : 0;
    int c = valid ? __ldg(ei + E + i) : 0;
    int seg = 0;
    for (int k = 0; k < nbe; k++) seg += (sbe[k] <= t) ? 1 : 0;
    int ns = nbe + 1;
    for (int s = 0; s < ns; s++) {
        unsigned mask = __ballot_sync(FULL, valid && (seg == s));
        if (mask) {
            int leader = __ffs(mask) - 1;
            int base = 0;
            if (lane == leader) base = atomicAdd(&g_ecnt[s], __popc(mask));
            base = __shfl_sync(FULL, base, leader);
            if (valid && seg == s) {
                int pos = base + __popc(mask & ((1u << lane) - 1u));
                g_ebuckp[s * EMAX + pos] = make_int4(r, c, __float_as_int(t), 0);
            }
        }
    }

    if (i < A) {
        float ta = __ldg(ang + i);
        int j = __ldg(ai + A + i);
        int sa = 0;
        for (int k = 0; k < nba; k++) sa += (sba[k] <= ta) ? 1 : 0;
        float2* p = &g_cts[sa * NMAX + j];
        atomicAdd(&p->x, 1.0f);
        atomicAdd(&p->y, ta);
    }
}

// ---------------------------------------------------------------------------
// K3: fused angle-expansion + edge kernel (unchanged from R9).
// ---------------------------------------------------------------------------
__global__ void __launch_bounds__(128, 4)
k_edge(const float* __restrict__ x, float* __restrict__ out, int N) {
    __shared__ __align__(16) float stage[4][128];
    __shared__ __align__(16) float stres[4][128];
    __shared__ float2 scts[ACH][128];
    int tid = threadIdx.x;
    int lane = tid & 31;
    int wi = tid >> 5;
    int gw = blockIdx.x * 4 + wi;
    int q_my = lane >> 3;
    int sub = lane & 7;

    // ================= Phase A: angle expansion =================
    int na = g_nseg_a;
    int j0 = blockIdx.x * 128;
    if (j0 < N) {
        int ce = na < ACH ? na : ACH;
        int jt = j0 + tid;
        for (int s = 0; s < ce; s++)
            scts[s][tid] = (jt < N) ? g_cts[s * NMAX + jt] : make_float2(0.f, 0.f);
        __syncthreads();

        float aAr[ACH], aBr[ACH];
        for (int s = 0; s < ce; s++) {
            aAr[s] = g_aA[s * 32 + lane];
            aBr[s] = g_aB[s * 32 + lane];
        }
        for (int g = 0; g < 8; g++) {
            int nb0 = wi * 32 + g * 4;
            #pragma unroll
            for (int q = 0; q < 4; q++) {
                float acc = 0.0f;
                for (int s = 0; s < ce; s++) {
                    float2 ct = scts[s][nb0 + q];
                    acc = fmaf(ct.x, aAr[s], acc);
                    acc = fmaf(ct.y, aBr[s], acc);
                }
                for (int s = ACH; s < na; s++) {
                    int jn = j0 + nb0 + q;
                    float2 ct = (jn < N) ? g_cts[s * NMAX + jn] : make_float2(0.f, 0.f);
                    acc = fmaf(ct.x, g_aA[s * 32 + lane], acc);
                    acc = fmaf(ct.y, g_aB[s * 32 + lane], acc);
                }
                stres[wi][q * 32 + lane] = acc;
            }
            __syncwarp();
            int node = j0 + nb0 + q_my;
            if (node < N) {
                float4 v = ((const float4*)stres[wi])[lane];
                float* dst = out + node * 32 + sub * 4;
                asm volatile("red.global.add.v4.f32 [%0], {%1, %2, %3, %4};"
                             :: "l"(dst), "f"(v.x), "f"(v.y), "f"(v.z), "f"(v.w)
                             : "memory");
            }
            __syncwarp();
        }
    }

    // ================= Phase B: edge branch =================
    int ns = g_nseg_e;
    for (int s = 0; s < ns; s++) {
        int cnt = g_ecnt[s];
        int idx = gw * 4;
        if (idx >= cnt) continue;

        ull abA[16], abB[16];
        const ull* T = g_AB + s * 1024;
        #pragma unroll
        for (int k = 0; k < 16; k++) {
            abA[k] = T[k * 32 + lane];
            abB[k] = T[512 + k * 32 + lane];
        }

        const int4* __restrict__ buck = g_ebuckp + s * EMAX;

        int ep = idx + q_my; if (ep > cnt - 1) ep = cnt - 1;
        int4 pm = __ldg(buck + ep);
        float4 xf = __ldg((const float4*)(x + pm.y * 32) + sub);

        while (idx < cnt) {
            ((float4*)stage[wi])[lane] = xf;
            __syncwarp();
            int cur = idx;
            idx += NWARP * 4;
            if (idx < cnt) {
                int en = idx + q_my; if (en > cnt - 1) en = cnt - 1;
                pm = __ldg(buck + en);
                xf = __ldg((const float4*)(x + pm.y * 32) + sub);
            }

            int m = cnt - 1;
            int4 p0 = __ldg(buck + cur);
            int4 p1 = __ldg(buck + (cur + 1 > m ? m : cur + 1));
            int4 p2 = __ldg(buck + (cur + 2 > m ? m : cur + 2));
            int4 p3 = __ldg(buck + (cur + 3 > m ? m : cur + 3));

            const ulonglong2* __restrict__ sv = (const ulonglong2*)stage[wi];
            ull aA0 = 0, aB0 = 0, aA1 = 0, aB1 = 0, aA2 = 0, aB2 = 0, aA3 = 0, aB3 = 0;
            #pragma unroll
            for (int j = 0; j < 8; j++) {
                ulonglong2 v0 = sv[j], v1 = sv[8 + j], v2 = sv[16 + j], v3 = sv[24 + j];
                asm("fma.rn.f32x2 %0, %1, %2, %0;" : "+l"(aA0) : "l"(v0.x), "l"(abA[2 * j]));
                asm("fma.rn.f32x2 %0, %1, %2, %0;" : "+l"(aB0) : "l"(v0.x), "l"(abB[2 * j]));
                asm("fma.rn.f32x2 %0, %1, %2, %0;" : "+l"(aA1) : "l"(v1.x), "l"(abA[2 * j]));
                asm("fma.rn.f32x2 %0, %1, %2, %0;" : "+l"(aB1) : "l"(v1.x), "l"(abB[2 * j]));
                asm("fma.rn.f32x2 %0, %1, %2, %0;" : "+l"(aA2) : "l"(v2.x), "l"(abA[2 * j]));
                asm("fma.rn.f32x2 %0, %1, %2, %0;" : "+l"(aB2) : "l"(v2.x), "l"(abB[2 * j]));
                asm("fma.rn.f32x2 %0, %1, %2, %0;" : "+l"(aA3) : "l"(v3.x), "l"(abA[2 * j]));
                asm("fma.rn.f32x2 %0, %1, %2, %0;" : "+l"(aB3) : "l"(v3.x), "l"(abB[2 * j]));
                asm("fma.rn.f32x2 %0, %1, %2, %0;" : "+l"(aA0) : "l"(v0.y), "l"(abA[2 * j + 1]));
                asm("fma.rn.f32x2 %0, %1, %2, %0;" : "+l"(aB0) : "l"(v0.y), "l"(abB[2 * j + 1]));
                asm("fma.rn.f32x2 %0, %1, %2, %0;" : "+l"(aA1) : "l"(v1.y), "l"(abA[2 * j + 1]));
                asm("fma.rn.f32x2 %0, %1, %2, %0;" : "+l"(aB1) : "l"(v1.y), "l"(abB[2 * j + 1]));
                asm("fma.rn.f32x2 %0, %1, %2, %0;" : "+l"(aA2) : "l"(v2.y), "l"(abA[2 * j + 1]));
                asm("fma.rn.f32x2 %0, %1, %2, %0;" : "+l"(aB2) : "l"(v2.y), "l"(abB[2 * j + 1]));
                asm("fma.rn.f32x2 %0, %1, %2, %0;" : "+l"(aA3) : "l"(v3.y), "l"(abA[2 * j + 1]));
                asm("fma.rn.f32x2 %0, %1, %2, %0;" : "+l"(aB3) : "l"(v3.y), "l"(abB[2 * j + 1]));
            }
            float alo, ahi, blo, bhi;
            asm("mov.b64 {%0, %1}, %2;" : "=f"(alo), "=f"(ahi) : "l"(aA0));
            asm("mov.b64 {%0, %1}, %2;" : "=f"(blo), "=f"(bhi) : "l"(aB0));
            stres[wi][lane] = fmaf(__int_as_float(p0.z), blo + bhi, alo + ahi);
            asm("mov.b64 {%0, %1}, %2;" : "=f"(alo), "=f"(ahi) : "l"(aA1));
            asm("mov.b64 {%0, %1}, %2;" : "=f"(blo), "=f"(bhi) : "l"(aB1));
            stres[wi][32 + lane] = fmaf(__int_as_float(p1.z), blo + bhi, alo + ahi);
            asm("mov.b64 {%0, %1}, %2;" : "=f"(alo), "=f"(ahi) : "l"(aA2));
            asm("mov.b64 {%0, %1}, %2;" : "=f"(blo), "=f"(bhi) : "l"(aB2));
            stres[wi][64 + lane] = fmaf(__int_as_float(p2.z), blo + bhi, alo + ahi);
            asm("mov.b64 {%0, %1}, %2;" : "=f"(alo), "=f"(ahi) : "l"(aA3));
            asm("mov.b64 {%0, %1}, %2;" : "=f"(blo), "=f"(bhi) : "l"(aB3));
            stres[wi][96 + lane] = fmaf(__int_as_float(p3.z), blo + bhi, alo + ahi);
            __syncwarp();

            int row = (q_my == 0) ? p0.x : (q_my == 1) ? p1.x : (q_my == 2) ? p2.x : p3.x;
            if (cur + q_my < cnt) {
                float4 v = ((const float4*)stres[wi])[lane];
                float* dst = out + row * 32 + sub * 4;
                asm volatile("red.global.add.v4.f32 [%0], {%1, %2, %3, %4};"
                             :: "l"(dst), "f"(v.x), "f"(v.y), "f"(v.z), "f"(v.w)
                             : "memory");
            }
            __syncwarp();
        }
    }
}

// ---------------------------------------------------------------------------
extern "C" void kernel_launch(void* const* d_in, const int* in_sizes, int n_in,
                              void* d_out, int out_size) {
    const float* x   = (const float*)d_in[0];
    const int*   ei  = (const int*)d_in[1];
    const float* ea  = (const float*)d_in[2];
    const int*   ai  = (const int*)d_in[3];
    const float* ang = (const float*)d_in[4];
    const float* eW1 = (const float*)d_in[5];
    const float* eb1 = (const float*)d_in[6];
    const float* eW2 = (const float*)d_in[7];
    const float* eb2 = (const float*)d_in[8];
    const float* aW1 = (const float*)d_in[9];
    const float* ab1 = (const float*)d_in[10];
    const float* aW2 = (const float*)d_in[11];
    const float* ab2 = (const float*)d_in[12];
    float* out = (float*)d_out;

    int N = in_sizes[0] / CH;
    int E = in_sizes[1] / 2;
    int A = in_sizes[3] / 3;

    k_setup<<<4 * SEGS + 1 + 256, 256>>>(eW1, eb1, eW2, eb2, aW1, ab1, aW2, ab2);
    int fb = ((E > A ? E : A) + 255) / 256;
    k_front<<<fb, 256>>>(ei, ea, ai, ang, out, E, A, N);
    k_edge<<<NBLK, 128>>>(x, out, N);
}

// round 11
// speedup vs baseline: 1.0476x; 1.0476x over previous
#include <cuda_runtime.h>

#define CH 32
#define SEGS 33
#define NMAX 50000
#define EMAX 200000
#define FULL 0xffffffffu
#define NBLK 592
#define NWARP (NBLK * 4)
#define ACH 8
#define TBLK (4 * SEGS)          // 132 table-build blocks
#define FSTART (TBLK + 1)        // front blocks begin here

typedef unsigned long long ull;

// ---- device-global scratch ----
__device__ int   g_nseg_e, g_nseg_a;              // effective segment counts
// per segment: [0,512) = PA pairs {A[2k][o],A[2k+1][o]}, [512,1024) = PB pairs
__device__ ull   g_AB[SEGS * 1024];
__device__ float g_aA[SEGS * 32], g_aB[SEGS * 32];
__device__ int   g_ecnt[SEGS];                    // zero at launch (self-cleaned)
__device__ int   g_done;                          // k_edge completion counter
__device__ __align__(16) int4 g_ebuckp[SEGS * EMAX]; // packed {row, col, t_bits, 0}
__device__ __align__(16) float2 g_cts[SEGS * NMAX];  // zero at launch (self-cleaned)

// ---------------------------------------------------------------------------
// warp-level breakpoint extraction + rank sort into `sorted`; returns count.
// ---------------------------------------------------------------------------
__device__ __forceinline__ int bp_sort(const float* __restrict__ W,
                                       const float* __restrict__ Bv,
                                       int lane, float* sorted) {
    float w = W[lane], b = Bv[lane];
    float p = (w != 0.0f) ? (-b / w) : -1.0f;
    bool valid = (p > 0.0f && p < 1.0f);
    unsigned vm = __ballot_sync(FULL, valid);
    int c = __popc(vm);
    int rank = 0;
    #pragma unroll
    for (int i = 0; i < 32; i++) {
        float pi = __shfl_sync(FULL, p, i);
        bool vi = (vm >> i) & 1u;
        if (vi && (pi < p || (pi == p && i < lane))) rank++;
    }
    if (valid) sorted[rank] = p;
    __syncwarp();
    return c;
}

// ---------------------------------------------------------------------------
// K1 (merged): blocks 0..131 = edge table (segment=blk>>2, io-chunk=blk&3);
//   block 132 = angle table + publish nseg counts;
//   blocks 133+ = front pass (out zeroing + edge bucketing + angle scatter),
//   breakpoints recomputed locally per block (no cross-block dependency).
// Requires g_ecnt/g_cts zero on entry (static init / k_edge self-clean).
// ---------------------------------------------------------------------------
__global__ void k_main(const float* __restrict__ eW1, const float* __restrict__ eb1,
                       const float* __restrict__ eW2, const float* __restrict__ eb2,
                       const float* __restrict__ aW1, const float* __restrict__ ab1,
                       const float* __restrict__ aW2, const float* __restrict__ ab2,
                       const int* __restrict__ ei, const float* __restrict__ ea,
                       const int* __restrict__ ai, const float* __restrict__ ang,
                       float* __restrict__ out, int E, int A, int N, int FB) {
    int blk = blockIdx.x;
    int tid = threadIdx.x;
    if (blk < TBLK) {
        // ---- edge table build ----
        int s = blk >> 2, chunk = blk & 3;
        __shared__ float sbp[33];
        __shared__ int scnt;
        __shared__ float w1[32], b1[32];
        if (tid < 32) {
            int c = bp_sort(eW1, eb1, tid, sbp);
            if (tid == 0) scnt = c;
        }
        if (tid >= 32 && tid < 64) {
            int l = tid - 32;
            w1[l] = eW1[l]; b1[l] = eb1[l];
        }
        __syncthreads();
        int c = scnt;
        if (s > c) return;
        float lo = (s == 0) ? 0.0f : sbp[s - 1];
        float hi = (s == c) ? 1.0f : sbp[s];
        float trep = 0.5f * (lo + hi);
        int io = chunk * 256 + tid;
        float a = eb2[io], b = 0.0f;
        #pragma unroll
        for (int k = 0; k < 32; k++) {
            if (w1[k] * trep + b1[k] > 0.0f) {
                float w2 = __ldg(eW2 + k * 1024 + io);
                a = fmaf(b1[k], w2, a);
                b = fmaf(w1[k], w2, b);
            }
        }
        int i = io >> 5, o = io & 31;
        int pa = s * 2048 + (i >> 1) * 64 + o * 2 + (i & 1);
        float* ABf = (float*)g_AB;
        ABf[pa] = a;
        ABf[pa + 1024] = b;
    } else if (blk == TBLK) {
        // ---- angle table + publish nseg counts ----
        __shared__ float se[33], sa[33];
        __shared__ int sca;
        int warp = tid >> 5, lane = tid & 31;
        if (warp == 0) {
            int c = bp_sort(eW1, eb1, lane, se);
            if (lane == 0) g_nseg_e = c + 1;
        } else if (warp == 1) {
            int c = bp_sort(aW1, ab1, lane, sa);
            if (lane == 0) { g_nseg_a = c + 1; sca = c; }
        }
        __syncthreads();
        int ca = sca;
        int ns = ca + 1;
        for (int idx = tid; idx < ns * 32; idx += blockDim.x) {
            int s2 = idx >> 5, o = idx & 31;
            float lo = (s2 == 0) ? 0.0f : sa[s2 - 1];
            float hi = (s2 == ca) ? 1.0f : sa[s2];
            float trep = 0.5f * (lo + hi);
            float a = ab2[o], b = 0.0f;
            #pragma unroll
            for (int k = 0; k < 32; k++) {
                float w = aW1[k], bb = ab1[k];
                if (w * trep + bb > 0.0f) {
                    float w2 = aW2[k * 32 + o];
                    a = fmaf(bb, w2, a);
                    b = fmaf(w, w2, b);
                }
            }
            g_aA[idx] = a;
            g_aB[idx] = b;
        }
    } else {
        // ---- front pass (local breakpoints) ----
        __shared__ float sbe[33], sba[33];
        __shared__ int snbe, snba;
        int warp = tid >> 5, lane = tid & 31;
        if (warp == 0) {
            int c = bp_sort(eW1, eb1, lane, sbe);
            if (lane == 0) snbe = c;
        } else if (warp == 1) {
            int c = bp_sort(aW1, ab1, lane, sba);
            if (lane == 0) snba = c;
        }
        __syncthreads();
        int nbe = snbe, nba = snba;
        int i = (blk - FSTART) * 256 + tid;

        // zero out (grid-stride over front blocks)
        {
            float4 z = make_float4(0.f, 0.f, 0.f, 0.f);
            int no = N * 8;
            int stride = FB * 256;
            float4* o4 = (float4*)out;
            for (int k = i; k < no; k += stride) o4[k] = z;
        }

        bool valid = (i < E);
        float t = valid ? __ldg(ea + i) : 0.0f;
        int r = valid ? __ldg(ei + i) : 0;
        int c = valid ? __ldg(ei + E + i) : 0;
        int seg = 0;
        for (int k = 0; k < nbe; k++) seg += (sbe[k] <= t) ? 1 : 0;
        int ns = nbe + 1;
        for (int s = 0; s < ns; s++) {
            unsigned mask = __ballot_sync(FULL, valid && (seg == s));
            if (mask) {
                int leader = __ffs(mask) - 1;
                int base = 0;
                if (lane == leader) base = atomicAdd(&g_ecnt[s], __popc(mask));
                base = __shfl_sync(FULL, base, leader);
                if (valid && seg == s) {
                    int pos = base + __popc(mask & ((1u << lane) - 1u));
                    g_ebuckp[s * EMAX + pos] = make_int4(r, c, __float_as_int(t), 0);
                }
            }
        }

        if (i < A) {
            float ta = __ldg(ang + i);
            int j = __ldg(ai + A + i);
            int sa2 = 0;
            for (int k = 0; k < nba; k++) sa2 += (sba[k] <= ta) ? 1 : 0;
            float2* p = &g_cts[sa2 * NMAX + j];
            atomicAdd(&p->x, 1.0f);
            atomicAdd(&p->y, ta);
        }
    }
}

// ---------------------------------------------------------------------------
// K2: fused angle-expansion + edge kernel, self-cleaning (zeroes the g_cts
//     slices it consumed; last block zeroes g_ecnt for the next replay).
// ---------------------------------------------------------------------------
__global__ void __launch_bounds__(128, 4)
k_edge(const float* __restrict__ x, float* __restrict__ out, int N) {
    __shared__ __align__(16) float stage[4][128];
    __shared__ __align__(16) float stres[4][128];
    __shared__ float2 scts[ACH][128];
    int tid = threadIdx.x;
    int lane = tid & 31;
    int wi = tid >> 5;
    int gw = blockIdx.x * 4 + wi;
    int q_my = lane >> 3;
    int sub = lane & 7;

    // ================= Phase A: angle expansion =================
    int na = g_nseg_a;
    int j0 = blockIdx.x * 128;
    int jt = j0 + tid;
    if (j0 < N) {
        int ce = na < ACH ? na : ACH;
        for (int s = 0; s < ce; s++)
            scts[s][tid] = (jt < N) ? g_cts[s * NMAX + jt] : make_float2(0.f, 0.f);
        __syncthreads();
        // self-clean the staged slice (re-read happens only from smem)
        float2 z2 = make_float2(0.f, 0.f);
        for (int s = 0; s < ce; s++)
            if (jt < N) g_cts[s * NMAX + jt] = z2;

        float aAr[ACH], aBr[ACH];
        for (int s = 0; s < ce; s++) {
            aAr[s] = g_aA[s * 32 + lane];
            aBr[s] = g_aB[s * 32 + lane];
        }
        for (int g = 0; g < 8; g++) {
            int nb0 = wi * 32 + g * 4;
            #pragma unroll
            for (int q = 0; q < 4; q++) {
                float acc = 0.0f;
                for (int s = 0; s < ce; s++) {
                    float2 ct = scts[s][nb0 + q];
                    acc = fmaf(ct.x, aAr[s], acc);
                    acc = fmaf(ct.y, aBr[s], acc);
                }
                for (int s = ACH; s < na; s++) {
                    int jn = j0 + nb0 + q;
                    float2 ct = (jn < N) ? g_cts[s * NMAX + jn] : make_float2(0.f, 0.f);
                    acc = fmaf(ct.x, g_aA[s * 32 + lane], acc);
                    acc = fmaf(ct.y, g_aB[s * 32 + lane], acc);
                }
                stres[wi][q * 32 + lane] = acc;
            }
            __syncwarp();
            int node = j0 + nb0 + q_my;
            if (node < N) {
                float4 v = ((const float4*)stres[wi])[lane];
                float* dst = out + node * 32 + sub * 4;
                asm volatile("red.global.add.v4.f32 [%0], {%1, %2, %3, %4};"
                             :: "l"(dst), "f"(v.x), "f"(v.y), "f"(v.z), "f"(v.w)
                             : "memory");
            }
            __syncwarp();
        }
        // self-clean overflow segments (after all reads of them)
        for (int s = ACH; s < na; s++)
            if (jt < N) g_cts[s * NMAX + jt] = z2;
    }

    // ================= Phase B: edge branch =================
    int ns = g_nseg_e;
    for (int s = 0; s < ns; s++) {
        int cnt = g_ecnt[s];
        int idx = gw * 4;
        if (idx >= cnt) continue;

        ull abA[16], abB[16];
        const ull* T = g_AB + s * 1024;
        #pragma unroll
        for (int k = 0; k < 16; k++) {
            abA[k] = T[k * 32 + lane];
            abB[k] = T[512 + k * 32 + lane];
        }

        const int4* __restrict__ buck = g_ebuckp + s * EMAX;

        int ep = idx + q_my; if (ep > cnt - 1) ep = cnt - 1;
        int4 pm = __ldg(buck + ep);
        float4 xf = __ldg((const float4*)(x + pm.y * 32) + sub);

        while (idx < cnt) {
            ((float4*)stage[wi])[lane] = xf;
            __syncwarp();
            int cur = idx;
            idx += NWARP * 4;
            if (idx < cnt) {
                int en = idx + q_my; if (en > cnt - 1) en = cnt - 1;
                pm = __ldg(buck + en);
                xf = __ldg((const float4*)(x + pm.y * 32) + sub);
            }

            int m = cnt - 1;
            int4 p0 = __ldg(buck + cur);
            int4 p1 = __ldg(buck + (cur + 1 > m ? m : cur + 1));
            int4 p2 = __ldg(buck + (cur + 2 > m ? m : cur + 2));
            int4 p3 = __ldg(buck + (cur + 3 > m ? m : cur + 3));

            const ulonglong2* __restrict__ sv = (const ulonglong2*)stage[wi];
            ull aA0 = 0, aB0 = 0, aA1 = 0, aB1 = 0, aA2 = 0, aB2 = 0, aA3 = 0, aB3 = 0;
            #pragma unroll
            for (int j = 0; j < 8; j++) {
                ulonglong2 v0 = sv[j], v1 = sv[8 + j], v2 = sv[16 + j], v3 = sv[24 + j];
                asm("fma.rn.f32x2 %0, %1, %2, %0;" : "+l"(aA0) : "l"(v0.x), "l"(abA[2 * j]));
                asm("fma.rn.f32x2 %0, %1, %2, %0;" : "+l"(aB0) : "l"(v0.x), "l"(abB[2 * j]));
                asm("fma.rn.f32x2 %0, %1, %2, %0;" : "+l"(aA1) : "l"(v1.x), "l"(abA[2 * j]));
                asm("fma.rn.f32x2 %0, %1, %2, %0;" : "+l"(aB1) : "l"(v1.x), "l"(abB[2 * j]));
                asm("fma.rn.f32x2 %0, %1, %2, %0;" : "+l"(aA2) : "l"(v2.x), "l"(abA[2 * j]));
                asm("fma.rn.f32x2 %0, %1, %2, %0;" : "+l"(aB2) : "l"(v2.x), "l"(abB[2 * j]));
                asm("fma.rn.f32x2 %0, %1, %2, %0;" : "+l"(aA3) : "l"(v3.x), "l"(abA[2 * j]));
                asm("fma.rn.f32x2 %0, %1, %2, %0;" : "+l"(aB3) : "l"(v3.x), "l"(abB[2 * j]));
                asm("fma.rn.f32x2 %0, %1, %2, %0;" : "+l"(aA0) : "l"(v0.y), "l"(abA[2 * j + 1]));
                asm("fma.rn.f32x2 %0, %1, %2, %0;" : "+l"(aB0) : "l"(v0.y), "l"(abB[2 * j + 1]));
                asm("fma.rn.f32x2 %0, %1, %2, %0;" : "+l"(aA1) : "l"(v1.y), "l"(abA[2 * j + 1]));
                asm("fma.rn.f32x2 %0, %1, %2, %0;" : "+l"(aB1) : "l"(v1.y), "l"(abB[2 * j + 1]));
                asm("fma.rn.f32x2 %0, %1, %2, %0;" : "+l"(aA2) : "l"(v2.y), "l"(abA[2 * j + 1]));
                asm("fma.rn.f32x2 %0, %1, %2, %0;" : "+l"(aB2) : "l"(v2.y), "l"(abB[2 * j + 1]));
                asm("fma.rn.f32x2 %0, %1, %2, %0;" : "+l"(aA3) : "l"(v3.y), "l"(abA[2 * j + 1]));
                asm("fma.rn.f32x2 %0, %1, %2, %0;" : "+l"(aB3) : "l"(v3.y), "l"(abB[2 * j + 1]));
            }
            float alo, ahi, blo, bhi;
            asm("mov.b64 {%0, %1}, %2;" : "=f"(alo), "=f"(ahi) : "l"(aA0));
            asm("mov.b64 {%0, %1}, %2;" : "=f"(blo), "=f"(bhi) : "l"(aB0));
            stres[wi][lane] = fmaf(__int_as_float(p0.z), blo + bhi, alo + ahi);
            asm("mov.b64 {%0, %1}, %2;" : "=f"(alo), "=f"(ahi) : "l"(aA1));
            asm("mov.b64 {%0, %1}, %2;" : "=f"(blo), "=f"(bhi) : "l"(aB1));
            stres[wi][32 + lane] = fmaf(__int_as_float(p1.z), blo + bhi, alo + ahi);
            asm("mov.b64 {%0, %1}, %2;" : "=f"(alo), "=f"(ahi) : "l"(aA2));
            asm("mov.b64 {%0, %1}, %2;" : "=f"(blo), "=f"(bhi) : "l"(aB2));
            stres[wi][64 + lane] = fmaf(__int_as_float(p2.z), blo + bhi, alo + ahi);
            asm("mov.b64 {%0, %1}, %2;" : "=f"(alo), "=f"(ahi) : "l"(aA3));
            asm("mov.b64 {%0, %1}, %2;" : "=f"(blo), "=f"(bhi) : "l"(aB3));
            stres[wi][96 + lane] = fmaf(__int_as_float(p3.z), blo + bhi, alo + ahi);
            __syncwarp();

            int row = (q_my == 0) ? p0.x : (q_my == 1) ? p1.x : (q_my == 2) ? p2.x : p3.x;
            if (cur + q_my < cnt) {
                float4 v = ((const float4*)stres[wi])[lane];
                float* dst = out + row * 32 + sub * 4;
                asm volatile("red.global.add.v4.f32 [%0], {%1, %2, %3, %4};"
                             :: "l"(dst), "f"(v.x), "f"(v.y), "f"(v.z), "f"(v.w)
                             : "memory");
            }
            __syncwarp();
        }
    }

    // ---- last-block cleanup: zero g_ecnt for the next replay ----
    __syncthreads();
    if (tid == 0) {
        __threadfence();
        int v = atomicAdd(&g_done, 1);
        if (v == gridDim.x - 1) {
            g_done = 0;
            #pragma unroll
            for (int s = 0; s < SEGS; s++) g_ecnt[s] = 0;
        }
    }
}

// ---------------------------------------------------------------------------
extern "C" void kernel_launch(void* const* d_in, const int* in_sizes, int n_in,
                              void* d_out, int out_size) {
    const float* x   = (const float*)d_in[0];
    const int*   ei  = (const int*)d_in[1];
    const float* ea  = (const float*)d_in[2];
    const int*   ai  = (const int*)d_in[3];
    const float* ang = (const float*)d_in[4];
    const float* eW1 = (const float*)d_in[5];
    const float* eb1 = (const float*)d_in[6];
    const float* eW2 = (const float*)d_in[7];
    const float* eb2 = (const float*)d_in[8];
    const float* aW1 = (const float*)d_in[9];
    const float* ab1 = (const float*)d_in[10];
    const float* aW2 = (const float*)d_in[11];
    const float* ab2 = (const float*)d_in[12];
    float* out = (float*)d_out;

    int N = in_sizes[0] / CH;
    int E = in_sizes[1] / 2;
    int A = in_sizes[3] / 3;

    int FB = ((E > A ? E : A) + 255) / 256;
    k_main<<<FSTART + FB, 256>>>(eW1, eb1, eW2, eb2, aW1, ab1, aW2, ab2,
                                 ei, ea, ai, ang, out, E, A, N, FB);
    k_edge<<<NBLK, 128>>>(x, out, N);
}

// round 12
// speedup vs baseline: 1.6532x; 1.5781x over previous
#include <cuda_runtime.h>

#define CH 32
#define SEGS 33
#define NMAX 50000
#define EMAX 200000
#define FULL 0xffffffffu
#define NBLK 592
#define NTHR 128
#define NWARP (NBLK * 4)
#define NT (NBLK * NTHR)
#define ACH 8
#define ER 3                    // edge rounds: ceil(200000 / 75776)
#define TBLK (8 * SEGS)         // 264 table-build blocks (s=blk>>3, chunk=blk&7)

typedef unsigned long long ull;

// ---- device-global scratch (zero-init; self-cleaned every launch) ----
__device__ ull   g_AB[SEGS * 1024];   // [0,512)=PA pairs, [512,1024)=PB pairs per seg
__device__ float g_aA[SEGS * 32], g_aB[SEGS * 32];
__device__ int   g_ecnt[SEGS];        // bucket cursors (zero at entry)
__device__ int   g_bar, g_done;       // grid barrier + completion counter
__device__ __align__(16) int4 g_ebuckp[SEGS * EMAX];  // {row, col, t_bits, 0}
__device__ __align__(16) float2 g_cts[SEGS * NMAX];   // (count, sum_t), zero at entry

// ---------------------------------------------------------------------------
__device__ __forceinline__ int bp_sort(const float* __restrict__ W,
                                       const float* __restrict__ Bv,
                                       int lane, float* sorted) {
    float w = W[lane], b = Bv[lane];
    float p = (w != 0.0f) ? (-b / w) : -1.0f;
    bool valid = (p > 0.0f && p < 1.0f);
    unsigned vm = __ballot_sync(FULL, valid);
    int c = __popc(vm);
    int rank = 0;
    #pragma unroll
    for (int i = 0; i < 32; i++) {
        float pi = __shfl_sync(FULL, p, i);
        bool vi = (vm >> i) & 1u;
        if (vi && (pi < p || (pi == p && i < lane))) rank++;
    }
    if (valid) sorted[rank] = p;
    __syncwarp();
    return c;
}

// ---------------------------------------------------------------------------
// Single persistent kernel: [phase 0: tables + bucketing + scatter + zeroing]
// -> grid barrier -> [phase 1: angle expansion + edge compute] -> self-clean.
// ---------------------------------------------------------------------------
__global__ void __launch_bounds__(NTHR, 4)
k_all(const float* __restrict__ x,
      const int* __restrict__ ei, const float* __restrict__ ea,
      const int* __restrict__ ai, const float* __restrict__ ang,
      const float* __restrict__ eW1, const float* __restrict__ eb1,
      const float* __restrict__ eW2, const float* __restrict__ eb2,
      const float* __restrict__ aW1, const float* __restrict__ ab1,
      const float* __restrict__ aW2, const float* __restrict__ ab2,
      float* __restrict__ out, int E, int A, int N) {
    __shared__ float sbe[33], sba[33];
    __shared__ int snbe, snba;
    __shared__ float w1[32], b1[32];
    __shared__ int bcnt[SEGS], gbase[SEGS], cpre[SEGS + 1];
    __shared__ __align__(16) float stage[4][NTHR];
    __shared__ __align__(16) float stresA[4][NTHR];
    __shared__ __align__(16) float stresB[4][NTHR];
    __shared__ float2 scts[ACH][NTHR];

    int tid = threadIdx.x, lane = tid & 31, warp = tid >> 5;
    int blk = blockIdx.x;
    int q_my = lane >> 3, sub = lane & 7;

    // ---- local breakpoints + weight copies ----
    if (warp == 0) {
        int c = bp_sort(eW1, eb1, lane, sbe);
        if (lane == 0) snbe = c;
    } else if (warp == 1) {
        int c = bp_sort(aW1, ab1, lane, sba);
        if (lane == 0) snba = c;
    } else if (warp == 2) {
        w1[lane] = eW1[lane];
        b1[lane] = eb1[lane];
    }
    if (tid < SEGS) bcnt[tid] = 0;
    __syncthreads();
    int nbe = snbe, nba = snba;

    // ================= Phase 0a: table build =================
    if (blk < TBLK) {
        int s = blk >> 3, chunk = blk & 7;
        if (s <= nbe) {
            float lo = (s == 0) ? 0.0f : sbe[s - 1];
            float hi = (s == nbe) ? 1.0f : sbe[s];
            float trep = 0.5f * (lo + hi);
            int io = chunk * NTHR + tid;
            float a = eb2[io], b = 0.0f;
            #pragma unroll
            for (int k = 0; k < 32; k++) {
                if (w1[k] * trep + b1[k] > 0.0f) {
                    float w2 = __ldg(eW2 + k * 1024 + io);
                    a = fmaf(b1[k], w2, a);
                    b = fmaf(w1[k], w2, b);
                }
            }
            int i = io >> 5, o = io & 31;
            int pa = s * 2048 + (i >> 1) * 64 + o * 2 + (i & 1);
            float* ABf = (float*)g_AB;
            ABf[pa] = a;
            ABf[pa + 1024] = b;
        }
    } else if (blk == TBLK) {
        int ca = nba, ns = ca + 1;
        for (int idx = tid; idx < ns * 32; idx += NTHR) {
            int s2 = idx >> 5, o = idx & 31;
            float lo = (s2 == 0) ? 0.0f : sba[s2 - 1];
            float hi = (s2 == ca) ? 1.0f : sba[s2];
            float trep = 0.5f * (lo + hi);
            float a = ab2[o], b = 0.0f;
            #pragma unroll
            for (int k = 0; k < 32; k++) {
                float w = aW1[k], bb = ab1[k];
                if (w * trep + bb > 0.0f) {
                    float w2 = aW2[k * 32 + o];
                    a = fmaf(bb, w2, a);
                    b = fmaf(w, w2, b);
                }
            }
            g_aA[idx] = a;
            g_aB[idx] = b;
        }
    }

    // ================= Phase 0b: zero out =================
    {
        float4 z = make_float4(0.f, 0.f, 0.f, 0.f);
        int no = N * 8;
        float4* o4 = (float4*)out;
        for (int k2 = blk * NTHR + tid; k2 < no; k2 += NT) o4[k2] = z;
    }

    // ================= Phase 0c: edge bucketing (block-aggregated) ==========
    int segR[ER], rnkR[ER];
    int4 pay[ER];
    #pragma unroll
    for (int r = 0; r < ER; r++) {
        int i = blk * NTHR + tid + r * NT;
        segR[r] = -1;
        if (i < E) {
            float t = __ldg(ea + i);
            int seg = 0;
            for (int k = 0; k < nbe; k++) seg += (sbe[k] <= t) ? 1 : 0;
            segR[r] = seg;
            rnkR[r] = atomicAdd(&bcnt[seg], 1);
            pay[r] = make_int4(__ldg(ei + i), __ldg(ei + E + i), __float_as_int(t), 0);
        }
    }
    __syncthreads();
    if (tid <= nbe) gbase[tid] = atomicAdd(&g_ecnt[tid], bcnt[tid]);
    __syncthreads();
    #pragma unroll
    for (int r = 0; r < ER; r++) {
        if (segR[r] >= 0)
            g_ebuckp[segR[r] * EMAX + gbase[segR[r]] + rnkR[r]] = pay[r];
    }

    // ================= Phase 0d: angle scatter =================
    for (int i = blk * NTHR + tid; i < A; i += NT) {
        float ta = __ldg(ang + i);
        int j = __ldg(ai + A + i);
        int sa2 = 0;
        for (int k = 0; k < nba; k++) sa2 += (sba[k] <= ta) ? 1 : 0;
        float2* p = &g_cts[sa2 * NMAX + j];
        atomicAdd(&p->x, 1.0f);
        atomicAdd(&p->y, ta);
    }

    // ================= grid barrier (all 592 blocks resident) =================
    __syncthreads();
    if (tid == 0) {
        __threadfence();
        atomicAdd(&g_bar, 1);
        while (atomicAdd(&g_bar, 0) < NBLK) __nanosleep(64);
        __threadfence();
    }
    __syncthreads();

    // ---- prefix sums over bucket counts ----
    if (tid == 0) {
        int acc = 0;
        for (int s2 = 0; s2 <= nbe; s2++) { cpre[s2] = acc; acc += g_ecnt[s2]; }
        cpre[nbe + 1] = acc;
    }
    __syncthreads();

    // ================= Phase 1a: angle expansion =================
    int na = nba + 1;
    int j0 = blk * NTHR;
    int jt = j0 + tid;
    float2 z2 = make_float2(0.f, 0.f);
    if (j0 < N) {
        int ce = na < ACH ? na : ACH;
        for (int s2 = 0; s2 < ce; s2++)
            scts[s2][tid] = (jt < N) ? g_cts[s2 * NMAX + jt] : z2;
        __syncthreads();
        for (int s2 = 0; s2 < ce; s2++)          // self-clean staged slices
            if (jt < N) g_cts[s2 * NMAX + jt] = z2;

        float aAr[ACH], aBr[ACH];
        for (int s2 = 0; s2 < ce; s2++) {
            aAr[s2] = g_aA[s2 * 32 + lane];
            aBr[s2] = g_aB[s2 * 32 + lane];
        }
        for (int g = 0; g < 8; g++) {
            int nb0 = warp * 32 + g * 4;
            #pragma unroll
            for (int q = 0; q < 4; q++) {
                float acc = 0.0f;
                for (int s2 = 0; s2 < ce; s2++) {
                    float2 ct = scts[s2][nb0 + q];
                    acc = fmaf(ct.x, aAr[s2], acc);
                    acc = fmaf(ct.y, aBr[s2], acc);
                }
                for (int s2 = ACH; s2 < na; s2++) {
                    int jn = j0 + nb0 + q;
                    float2 ct = (jn < N) ? g_cts[s2 * NMAX + jn] : z2;
                    acc = fmaf(ct.x, g_aA[s2 * 32 + lane], acc);
                    acc = fmaf(ct.y, g_aB[s2 * 32 + lane], acc);
                }
                stresA[warp][q * 32 + lane] = acc;
            }
            __syncwarp();
            int node = j0 + nb0 + q_my;
            if (node < N) {
                float4 v = ((const float4*)stresA[warp])[lane];
                float* dst = out + node * 32 + sub * 4;
                asm volatile("red.global.add.v4.f32 [%0], {%1, %2, %3, %4};"
                             :: "l"(dst), "f"(v.x), "f"(v.y), "f"(v.z), "f"(v.w)
                             : "memory");
            }
            __syncwarp();
        }
        for (int s2 = ACH; s2 < na; s2++)        // clean overflow segments
            if (jt < N) g_cts[s2 * NMAX + jt] = z2;
    }

    // ================= Phase 1b: edge compute (contiguous partition) =========
    {
        int ns = nbe + 1;
        int Etot = cpre[ns];
        int gwarp = blk * 4 + warp;
        int Tw = (Etot + NWARP - 1) / NWARP;
        int lo = gwarp * Tw;
        int hi = lo + Tw; if (hi > Etot) hi = Etot;
        int s = 0;
        const float4* __restrict__ x4 = (const float4*)x;

        while (lo < hi) {
            while (cpre[s + 1] <= lo) s++;
            int seg_end = cpre[s + 1] < hi ? cpre[s + 1] : hi;
            int run = seg_end - lo;
            int local = lo - cpre[s];

            ull abA[16], abB[16];
            const ull* Tt = g_AB + s * 1024;
            #pragma unroll
            for (int k = 0; k < 16; k++) {
                abA[k] = Tt[k * 32 + lane];
                abB[k] = Tt[512 + k * 32 + lane];
            }
            const int4* __restrict__ buck = g_ebuckp + s * EMAX;
            int idx = local, end = local + run, last = end - 1;
            int pe = idx + q_my; if (pe > last) pe = last;
            int4 pm = __ldg(buck + pe);
            float4 xf = __ldg(x4 + pm.y * 8 + sub);

            while (idx < end) {
                ((float4*)stage[warp])[lane] = xf;
                __syncwarp();
                int rowc = pm.x;
                float tc = __int_as_float(pm.z);
                bool mine = (idx + q_my < end);
                idx += 4;
                if (idx < end) {
                    pe = idx + q_my; if (pe > last) pe = last;
                    pm = __ldg(buck + pe);
                    xf = __ldg(x4 + pm.y * 8 + sub);
                }

                const ulonglong2* __restrict__ sv = (const ulonglong2*)stage[warp];
                ull aA0 = 0, aB0 = 0, aA1 = 0, aB1 = 0, aA2 = 0, aB2 = 0, aA3 = 0, aB3 = 0;
                #pragma unroll
                for (int j = 0; j < 8; j++) {
                    ulonglong2 v0 = sv[j], v1 = sv[8 + j], v2 = sv[16 + j], v3 = sv[24 + j];
                    asm("fma.rn.f32x2 %0, %1, %2, %0;" : "+l"(aA0) : "l"(v0.x), "l"(abA[2 * j]));
                    asm("fma.rn.f32x2 %0, %1, %2, %0;" : "+l"(aB0) : "l"(v0.x), "l"(abB[2 * j]));
                    asm("fma.rn.f32x2 %0, %1, %2, %0;" : "+l"(aA1) : "l"(v1.x), "l"(abA[2 * j]));
                    asm("fma.rn.f32x2 %0, %1, %2, %0;" : "+l"(aB1) : "l"(v1.x), "l"(abB[2 * j]));
                    asm("fma.rn.f32x2 %0, %1, %2, %0;" : "+l"(aA2) : "l"(v2.x), "l"(abA[2 * j]));
                    asm("fma.rn.f32x2 %0, %1, %2, %0;" : "+l"(aB2) : "l"(v2.x), "l"(abB[2 * j]));
                    asm("fma.rn.f32x2 %0, %1, %2, %0;" : "+l"(aA3) : "l"(v3.x), "l"(abA[2 * j]));
                    asm("fma.rn.f32x2 %0, %1, %2, %0;" : "+l"(aB3) : "l"(v3.x), "l"(abB[2 * j]));
                    asm("fma.rn.f32x2 %0, %1, %2, %0;" : "+l"(aA0) : "l"(v0.y), "l"(abA[2 * j + 1]));
                    asm("fma.rn.f32x2 %0, %1, %2, %0;" : "+l"(aB0) : "l"(v0.y), "l"(abB[2 * j + 1]));
                    asm("fma.rn.f32x2 %0, %1, %2, %0;" : "+l"(aA1) : "l"(v1.y), "l"(abA[2 * j + 1]));
                    asm("fma.rn.f32x2 %0, %1, %2, %0;" : "+l"(aB1) : "l"(v1.y), "l"(abB[2 * j + 1]));
                    asm("fma.rn.f32x2 %0, %1, %2, %0;" : "+l"(aA2) : "l"(v2.y), "l"(abA[2 * j + 1]));
                    asm("fma.rn.f32x2 %0, %1, %2, %0;" : "+l"(aB2) : "l"(v2.y), "l"(abB[2 * j + 1]));
                    asm("fma.rn.f32x2 %0, %1, %2, %0;" : "+l"(aA3) : "l"(v3.y), "l"(abA[2 * j + 1]));
                    asm("fma.rn.f32x2 %0, %1, %2, %0;" : "+l"(aB3) : "l"(v3.y), "l"(abB[2 * j + 1]));
                }
                float alo, ahi, blo, bhi;
                asm("mov.b64 {%0, %1}, %2;" : "=f"(alo), "=f"(ahi) : "l"(aA0));
                asm("mov.b64 {%0, %1}, %2;" : "=f"(blo), "=f"(bhi) : "l"(aB0));
                stresA[warp][lane] = alo + ahi;
                stresB[warp][lane] = blo + bhi;
                asm("mov.b64 {%0, %1}, %2;" : "=f"(alo), "=f"(ahi) : "l"(aA1));
                asm("mov.b64 {%0, %1}, %2;" : "=f"(blo), "=f"(bhi) : "l"(aB1));
                stresA[warp][32 + lane] = alo + ahi;
                stresB[warp][32 + lane] = blo + bhi;
                asm("mov.b64 {%0, %1}, %2;" : "=f"(alo), "=f"(ahi) : "l"(aA2));
                asm("mov.b64 {%0, %1}, %2;" : "=f"(blo), "=f"(bhi) : "l"(aB2));
                stresA[warp][64 + lane] = alo + ahi;
                stresB[warp][64 + lane] = blo + bhi;
                asm("mov.b64 {%0, %1}, %2;" : "=f"(alo), "=f"(ahi) : "l"(aA3));
                asm("mov.b64 {%0, %1}, %2;" : "=f"(blo), "=f"(bhi) : "l"(aB3));
                stresA[warp][96 + lane] = alo + ahi;
                stresB[warp][96 + lane] = blo + bhi;
                __syncwarp();

                if (mine) {
                    float4 vA = ((const float4*)stresA[warp])[lane];
                    float4 vB = ((const float4*)stresB[warp])[lane];
                    float4 v;
                    v.x = fmaf(tc, vB.x, vA.x);
                    v.y = fmaf(tc, vB.y, vA.y);
                    v.z = fmaf(tc, vB.z, vA.z);
                    v.w = fmaf(tc, vB.w, vA.w);
                    float* dst = out + rowc * 32 + sub * 4;
                    asm volatile("red.global.add.v4.f32 [%0], {%1, %2, %3, %4};"
                                 :: "l"(dst), "f"(v.x), "f"(v.y), "f"(v.z), "f"(v.w)
                                 : "memory");
                }
                __syncwarp();
            }
            lo = seg_end;
        }
    }

    // ================= self-clean for next replay =================
    __syncthreads();
    if (tid == 0) {
        __threadfence();
        int v = atomicAdd(&g_done, 1);
        if (v == NBLK - 1) {
            g_done = 0;
            g_bar = 0;
            #pragma unroll
            for (int s2 = 0; s2 < SEGS; s2++) g_ecnt[s2] = 0;
        }
    }
}

// ---------------------------------------------------------------------------
extern "C" void kernel_launch(void* const* d_in, const int* in_sizes, int n_in,
                              void* d_out, int out_size) {
    const float* x   = (const float*)d_in[0];
    const int*   ei  = (const int*)d_in[1];
    const float* ea  = (const float*)d_in[2];
    const int*   ai  = (const int*)d_in[3];
    const float* ang = (const float*)d_in[4];
    const float* eW1 = (const float*)d_in[5];
    const float* eb1 = (const float*)d_in[6];
    const float* eW2 = (const float*)d_in[7];
    const float* eb2 = (const float*)d_in[8];
    const float* aW1 = (const float*)d_in[9];
    const float* ab1 = (const float*)d_in[10];
    const float* aW2 = (const float*)d_in[11];
    const float* ab2 = (const float*)d_in[12];
    float* out = (float*)d_out;

    int N = in_sizes[0] / CH;
    int E = in_sizes[1] / 2;
    int A = in_sizes[3] / 3;

    k_all<<<NBLK, NTHR>>>(x, ei, ea, ai, ang, eW1, eb1, eW2, eb2,
                          aW1, ab1, aW2, ab2, out, E, A, N);
}